// round 3
// baseline (speedup 1.0000x reference)
#include <cuda_runtime.h>

// Problem shape fixed by setup_inputs(): B=16, C=1024, H=W=32, NH=16.
#define B_  16
#define C_  1024
#define H_  32
#define W_  32
#define HW_ (H_*W_)
#define NH_ 16
#define P_  (H_*W_)       // 1024
#define N_  (P_+1)        // 1025
#define K_  10

// Scratch (__device__ globals; no allocations allowed)
__device__ int            g_idx[B_][K_];        // top-k positions
__device__ int            g_cpos[B_][K_];       // center pos (== g_idx)
__device__ int            g_nbr[B_][K_][8];     // clipped neighbor pos
__device__ unsigned short g_map[B_][P_];        // 0=copy, 0x8000|slot=center, 0x4000|(slot<<3)|j=winner
__device__ float          g_w[B_][K_][8];       // softmax weights
__device__ float          g_str[B_][K_][8];     // suppression strengths

__constant__ int c_dy[8] = {-1,-1,-1, 0, 0, 1, 1, 1};
__constant__ int c_dx[8] = {-1, 0, 1,-1, 1,-1, 0, 1};

// ---------------------------------------------------------------------------
// Kernel A: per-batch ratio -> warp top-10 -> winner bitmask -> fixup map.
// grid = B blocks, 1024 threads.
// ---------------------------------------------------------------------------
__global__ void __launch_bounds__(1024) plan_kernel(const float* __restrict__ attn) {
    int b = blockIdx.x;
    int t = threadIdx.x;            // == spatial position p

    __shared__ float s_ratio[P_];

    // zero the fixup map (set entries written after the barrier)
    g_map[b][t] = 0;

    // ratio[p] = mean_h attn[b,h,0,1+p] / (mean_h attn[b,h,1+p,1+p] + 1e-8)
    {
        const float* base = attn + (size_t)b * NH_ * (size_t)N_ * N_;
        size_t diag = (size_t)(1 + t) * (N_ + 1);
        float cls = 0.f, slf = 0.f;
#pragma unroll
        for (int h = 0; h < NH_; h++) {
            const float* a = base + (size_t)h * N_ * N_;
            cls += a[1 + t];
            slf += a[diag];
        }
        cls *= (1.f / NH_);
        slf *= (1.f / NH_);
        s_ratio[t] = cls / (slf + 1e-8f);
    }
    __syncthreads();

    if (t < 32) {
        int lane = t;
        // 32 keys per lane; ratio >= 0 so float bits are monotonic as unsigned.
        unsigned long long key[32];
#pragma unroll
        for (int u = 0; u < 32; u++) {
            int p = u * 32 + lane;
            key[u] = ((unsigned long long)__float_as_uint(s_ratio[p]) << 32)
                   | (unsigned)(0xFFFFFFFFu - (unsigned)p);   // tie -> smaller index
        }
        int sel[K_];
#pragma unroll
        for (int k = 0; k < K_; k++) {
            unsigned long long lm = 0ull; int li = 0;
#pragma unroll
            for (int u = 0; u < 32; u++)
                if (key[u] > lm) { lm = key[u]; li = u; }
            unsigned long long wm = lm;
#pragma unroll
            for (int off = 16; off; off >>= 1) {
                unsigned long long o = __shfl_xor_sync(0xffffffffu, wm, off);
                if (o > wm) wm = o;
            }
            if (lm == wm) key[li] = 0ull;           // unique: index embedded in key
            sel[k] = (int)(0xFFFFFFFFu - (unsigned)(wm & 0xFFFFFFFFull));
        }

        if (lane == 0) {
            int rr[K_], cc[K_];
            int ny[K_][8], nx[K_][8];
#pragma unroll
            for (int i = 0; i < K_; i++) {
                g_idx[b][i]  = sel[i];
                g_cpos[b][i] = sel[i];
                rr[i] = sel[i] / W_; cc[i] = sel[i] % W_;
#pragma unroll
                for (int j = 0; j < 8; j++) {
                    int y = rr[i] + c_dy[j]; y = y < 0 ? 0 : (y > H_ - 1 ? H_ - 1 : y);
                    int x = cc[i] + c_dx[j]; x = x < 0 ? 0 : (x > W_ - 1 ? W_ - 1 : x);
                    ny[i][j] = y; nx[i][j] = x;
                    g_nbr[b][i][j] = y * W_ + x;
                }
            }
            // Last-writer-wins: walk slots from highest k down; first claimant of
            // a non-center position is the reference loop's last writer.
            int cy[K_ * 8], cx[K_ * 8]; int ncl = 0;
            for (int k = K_ * 8 - 1; k >= 0; k--) {
                int i = k >> 3, j = k & 7;
                int y = ny[i][j], x = nx[i][j];
                bool skip = false;
                for (int m = 0; m < K_; m++)
                    if (y == rr[m] && x == cc[m]) { skip = true; break; }  // centers end as wavg
                if (skip) continue;
                for (int m = 0; m < ncl; m++)
                    if (cy[m] == y && cx[m] == x) { skip = true; break; }  // later slot already wrote
                if (skip) continue;
                cy[ncl] = y; cx[ncl] = x; ncl++;
                g_map[b][y * W_ + x] = (unsigned short)(0x4000u | (i << 3) | j);
            }
            for (int i = 0; i < K_; i++)
                g_map[b][sel[i]] = (unsigned short)(0x8000u | i);
        }
    }
}

// ---------------------------------------------------------------------------
// Kernel B: stats per (b,slot): 17 block sums -> w[8], str[8]. Read-only fm.
// grid = B*K blocks, 256 threads, 4 channels/thread (MLP=36).
// ---------------------------------------------------------------------------
__global__ void __launch_bounds__(256) stats_kernel(const float* __restrict__ fm) {
    int blk = blockIdx.x;
    int b = blk / K_, i = blk % K_;
    int cpos = g_cpos[b][i];
    int np[8];
#pragma unroll
    for (int j = 0; j < 8; j++) np[j] = g_nbr[b][i][j];

    const float* f = fm + (size_t)b * C_ * HW_;
    int t = threadIdx.x;

    float dot[8] = {0,0,0,0,0,0,0,0};
    float n2[8]  = {0,0,0,0,0,0,0,0};
    float o2 = 0.f;

#pragma unroll
    for (int u = 0; u < 4; u++) {
        int ch = t + u * 256;
        const float* fc = f + (size_t)ch * HW_;
        float v = fc[cpos];
        o2 += v * v;
#pragma unroll
        for (int j = 0; j < 8; j++) {
            float nv = fc[np[j]];
            dot[j] += nv * v;
            n2[j]  += nv * nv;
        }
    }

    __shared__ float part[17][8];
    float vals[17];
    vals[0] = o2;
#pragma unroll
    for (int j = 0; j < 8; j++) { vals[1 + j] = dot[j]; vals[9 + j] = n2[j]; }
#pragma unroll
    for (int k = 0; k < 17; k++) {
        float v = vals[k];
#pragma unroll
        for (int off = 16; off; off >>= 1) v += __shfl_down_sync(0xffffffffu, v, off);
        if ((t & 31) == 0) part[k][t >> 5] = v;
    }
    __syncthreads();

    if (t == 0) {
        float sums[17];
#pragma unroll
        for (int k = 0; k < 17; k++) {
            float s = 0.f;
#pragma unroll
            for (int wrp = 0; wrp < 8; wrp++) s += part[k][wrp];
            sums[k] = s;
        }
        float on = fmaxf(sqrtf(sums[0]), 1e-12f);
        float sim[8], z[8];
        float zmax = -1e30f;
#pragma unroll
        for (int j = 0; j < 8; j++) {
            float nn = fmaxf(sqrtf(sums[9 + j]), 1e-12f);
            sim[j] = sums[1 + j] / (nn * on);
            z[j] = fmaxf(1.f - sim[j], 0.f);
            zmax = fmaxf(zmax, z[j]);
        }
        float es = 0.f, e[8];
#pragma unroll
        for (int j = 0; j < 8; j++) { e[j] = expf(z[j] - zmax); es += e[j]; }
        float inv = 1.f / es;
#pragma unroll
        for (int j = 0; j < 8; j++) {
            g_w[b][i][j]   = e[j] * inv;
            g_str[b][i][j] = fminf(fmaxf(sim[j] * 0.1f, 0.f), 1.f);
        }
    }
}

// ---------------------------------------------------------------------------
// Kernel C: fused copy + fixup. One block per (b, channel) row of 1024 floats.
// Stage row in smem; specials (<=90 positions, same for every row of a batch)
// recomputed from smem; all writes are full coalesced float4 sectors.
// grid = B*C = 16384 blocks, 256 threads.
// ---------------------------------------------------------------------------
__global__ void __launch_bounds__(256) apply_kernel(const float* __restrict__ fm,
                                                    float* __restrict__ out) {
    int b  = blockIdx.x >> 10;
    int ch = blockIdx.x & 1023;
    int t  = threadIdx.x;

    const float4* src = (const float4*)(fm  + ((size_t)b * C_ + ch) * HW_);
    float4*       dst = (float4*)      (out + ((size_t)b * C_ + ch) * HW_);

    __shared__ float row[P_];
    __shared__ float s_w[K_ * 8], s_str[K_ * 8];
    __shared__ int   s_nbr[K_ * 8];
    __shared__ int   s_cpos[K_];

    float4 v = src[t];
    ((float4*)row)[t] = v;
    if (t < K_ * 8) {
        s_w[t]   = ((const float*)g_w[b])[t];
        s_str[t] = ((const float*)g_str[b])[t];
        s_nbr[t] = ((const int*)g_nbr[b])[t];
        if (t < K_) s_cpos[t] = g_cpos[b][t];
    }
    __syncthreads();

    const unsigned short* mp = g_map[b] + t * 4;
    float ov[4] = {v.x, v.y, v.z, v.w};
    float res[4];
#pragma unroll
    for (int u = 0; u < 4; u++) {
        unsigned short mv = mp[u];
        float r = ov[u];
        if (mv) {
            if (mv & 0x8000u) {                     // center -> weighted avg
                int slot = mv & 0xFF;
                float acc = 0.f;
#pragma unroll
                for (int j = 0; j < 8; j++)
                    acc += s_w[slot * 8 + j] * row[s_nbr[slot * 8 + j]];
                r = acc;
            } else {                                // winner -> nbr - str*center
                int slot = (mv >> 3) & 15;
                int j    = mv & 7;
                r = r - s_str[slot * 8 + j] * row[s_cpos[slot]];
            }
        }
        res[u] = r;
    }
    dst[t] = make_float4(res[0], res[1], res[2], res[3]);
}

// ---------------------------------------------------------------------------
extern "C" void kernel_launch(void* const* d_in, const int* in_sizes, int n_in,
                              void* d_out, int out_size) {
    const float* fm   = (const float*)d_in[0];
    const float* attn = (const float*)d_in[1];
    float* out = (float*)d_out;

    plan_kernel<<<B_, 1024>>>(attn);
    stats_kernel<<<B_ * K_, 256>>>(fm);
    apply_kernel<<<B_ * C_, 256>>>(fm, out);
}

// round 4
// speedup vs baseline: 1.0879x; 1.0879x over previous
#include <cuda_runtime.h>

// Problem shape fixed by setup_inputs(): B=16, C=1024, H=W=32, NH=16.
#define B_  16
#define C_  1024
#define H_  32
#define W_  32
#define HW_ (H_*W_)
#define NH_ 16
#define P_  (H_*W_)       // 1024
#define N_  (P_+1)        // 1025
#define K_  10

// Scratch (__device__ globals; no allocations allowed)
__device__ float          g_ratio[B_][P_];
__device__ int            g_cpos[B_][K_];       // center positions (top-k)
__device__ int            g_nbr[B_][K_][8];     // clipped neighbor positions
__device__ unsigned short g_map[B_][P_];        // 0=copy, 0x8000|slot=center, 0x4000|(slot<<3)|j=winner
__device__ float          g_w[B_][K_][8];       // softmax weights
__device__ float          g_str[B_][K_][8];     // suppression strengths

__constant__ int c_dy[8] = {-1,-1,-1, 0, 0, 1, 1, 1};
__constant__ int c_dx[8] = {-1, 0, 1,-1, 1,-1, 0, 1};

// ---------------------------------------------------------------------------
// Kernel 1: ratio. One thread per (b,h,p-chunk element): grid (B,16), 1024 thr
// = 64 positions x 16 heads. Each thread: 2 independent loads. Full-chip MLP.
// ---------------------------------------------------------------------------
__global__ void __launch_bounds__(1024) ratio_kernel(const float* __restrict__ attn) {
    int b  = blockIdx.x;
    int pc = blockIdx.y;            // chunk of 64 positions
    int t  = threadIdx.x;
    int h  = t >> 6;                // 0..15
    int pl = t & 63;                // 0..63
    int p  = pc * 64 + pl;

    const float* a = attn + (size_t)(b * NH_ + h) * N_ * N_;
    float cls = a[1 + p];                         // row 0, coalesced
    float slf = a[(size_t)(1 + p) * (N_ + 1)];    // diagonal, strided

    __shared__ float sc[NH_][64];
    __shared__ float ss[NH_][64];
    sc[h][pl] = cls;
    ss[h][pl] = slf;
    __syncthreads();

#pragma unroll
    for (int s = NH_ / 2; s >= 1; s >>= 1) {
        if (h < s) {
            sc[h][pl] += sc[h + s][pl];
            ss[h][pl] += ss[h + s][pl];
        }
        __syncthreads();
    }

    if (h == 0) {
        float c = sc[0][pl] * (1.f / NH_);
        float s0 = ss[0][pl] * (1.f / NH_);
        g_ratio[b][p] = c / (s0 + 1e-8f);
        // also pre-zero the fixup map (topk kernel sets the special entries)
        g_map[b][p] = 0;
    }
}

// ---------------------------------------------------------------------------
// Kernel 2: warp-per-batch top-10 in registers, then winner bitmask + fixup
// map on lane 0. grid = B blocks of 32 threads.
// ---------------------------------------------------------------------------
__global__ void topk_kernel() {
    int b = blockIdx.x;
    int lane = threadIdx.x;

    // 32 keys per lane; ratio >= 0 so float bits are monotonic as unsigned.
    unsigned long long key[32];
#pragma unroll
    for (int u = 0; u < 32; u++) {
        int p = u * 32 + lane;
        key[u] = ((unsigned long long)__float_as_uint(g_ratio[b][p]) << 32)
               | (unsigned)(0xFFFFFFFFu - (unsigned)p);   // tie -> smaller index
    }
    int sel[K_];
#pragma unroll
    for (int k = 0; k < K_; k++) {
        unsigned long long lm = 0ull; int li = 0;
#pragma unroll
        for (int u = 0; u < 32; u++)
            if (key[u] > lm) { lm = key[u]; li = u; }
        unsigned long long wm = lm;
#pragma unroll
        for (int off = 16; off; off >>= 1) {
            unsigned long long o = __shfl_xor_sync(0xffffffffu, wm, off);
            if (o > wm) wm = o;
        }
        if (lm == wm) key[li] = 0ull;           // unique: index embedded in key
        sel[k] = (int)(0xFFFFFFFFu - (unsigned)(wm & 0xFFFFFFFFull));
    }

    if (lane == 0) {
        int rr[K_], cc[K_];
        int ny[K_][8], nx[K_][8];
#pragma unroll
        for (int i = 0; i < K_; i++) {
            g_cpos[b][i] = sel[i];
            rr[i] = sel[i] / W_; cc[i] = sel[i] % W_;
#pragma unroll
            for (int j = 0; j < 8; j++) {
                int y = rr[i] + c_dy[j]; y = y < 0 ? 0 : (y > H_ - 1 ? H_ - 1 : y);
                int x = cc[i] + c_dx[j]; x = x < 0 ? 0 : (x > W_ - 1 ? W_ - 1 : x);
                ny[i][j] = y; nx[i][j] = x;
                g_nbr[b][i][j] = y * W_ + x;
            }
        }
        // Last-writer-wins: walk slots from highest k down; first claimant of
        // a non-center position is the reference loop's last writer.
        int cy[K_ * 8], cx[K_ * 8]; int ncl = 0;
        for (int k = K_ * 8 - 1; k >= 0; k--) {
            int i = k >> 3, j = k & 7;
            int y = ny[i][j], x = nx[i][j];
            bool skip = false;
            for (int m = 0; m < K_; m++)
                if (y == rr[m] && x == cc[m]) { skip = true; break; }  // centers end as wavg
            if (skip) continue;
            for (int m = 0; m < ncl; m++)
                if (cy[m] == y && cx[m] == x) { skip = true; break; }  // later slot already wrote
            if (skip) continue;
            cy[ncl] = y; cx[ncl] = x; ncl++;
            g_map[b][y * W_ + x] = (unsigned short)(0x4000u | (i << 3) | j);
        }
        for (int i = 0; i < K_; i++)
            g_map[b][sel[i]] = (unsigned short)(0x8000u | i);
    }
}

// ---------------------------------------------------------------------------
// Kernel 3: stats per (b,slot): 17 block sums -> w[8], str[8]. Read-only fm.
// grid = B*K blocks, 256 threads, 4 channels/thread (MLP=36).
// ---------------------------------------------------------------------------
__global__ void __launch_bounds__(256) stats_kernel(const float* __restrict__ fm) {
    int blk = blockIdx.x;
    int b = blk / K_, i = blk % K_;
    int cpos = g_cpos[b][i];
    int np[8];
#pragma unroll
    for (int j = 0; j < 8; j++) np[j] = g_nbr[b][i][j];

    const float* f = fm + (size_t)b * C_ * HW_;
    int t = threadIdx.x;

    float dot[8] = {0,0,0,0,0,0,0,0};
    float n2[8]  = {0,0,0,0,0,0,0,0};
    float o2 = 0.f;

#pragma unroll
    for (int u = 0; u < 4; u++) {
        int ch = t + u * 256;
        const float* fc = f + (size_t)ch * HW_;
        float v = fc[cpos];
        o2 += v * v;
#pragma unroll
        for (int j = 0; j < 8; j++) {
            float nv = fc[np[j]];
            dot[j] += nv * v;
            n2[j]  += nv * nv;
        }
    }

    __shared__ float part[17][8];
    float vals[17];
    vals[0] = o2;
#pragma unroll
    for (int j = 0; j < 8; j++) { vals[1 + j] = dot[j]; vals[9 + j] = n2[j]; }
#pragma unroll
    for (int k = 0; k < 17; k++) {
        float v = vals[k];
#pragma unroll
        for (int off = 16; off; off >>= 1) v += __shfl_down_sync(0xffffffffu, v, off);
        if ((t & 31) == 0) part[k][t >> 5] = v;
    }
    __syncthreads();

    if (t == 0) {
        float sums[17];
#pragma unroll
        for (int k = 0; k < 17; k++) {
            float s = 0.f;
#pragma unroll
            for (int wrp = 0; wrp < 8; wrp++) s += part[k][wrp];
            sums[k] = s;
        }
        float on = fmaxf(sqrtf(sums[0]), 1e-12f);
        float sim[8], z[8];
        float zmax = -1e30f;
#pragma unroll
        for (int j = 0; j < 8; j++) {
            float nn = fmaxf(sqrtf(sums[9 + j]), 1e-12f);
            sim[j] = sums[1 + j] / (nn * on);
            z[j] = fmaxf(1.f - sim[j], 0.f);
            zmax = fmaxf(zmax, z[j]);
        }
        float es = 0.f, e[8];
#pragma unroll
        for (int j = 0; j < 8; j++) { e[j] = expf(z[j] - zmax); es += e[j]; }
        float inv = 1.f / es;
#pragma unroll
        for (int j = 0; j < 8; j++) {
            g_w[b][i][j]   = e[j] * inv;
            g_str[b][i][j] = fminf(fmaxf(sim[j] * 0.1f, 0.f), 1.f);
        }
    }
}

// ---------------------------------------------------------------------------
// Kernel 4: fused copy + fixup. One block per (b, channel) row of 1024 floats.
// Stage row in smem; specials recomputed from smem (neighbors are in-row);
// all writes are full coalesced float4 sectors.
// grid = B*C = 16384 blocks, 256 threads.
// ---------------------------------------------------------------------------
__global__ void __launch_bounds__(256) apply_kernel(const float* __restrict__ fm,
                                                    float* __restrict__ out) {
    int b  = blockIdx.x >> 10;
    int ch = blockIdx.x & 1023;
    int t  = threadIdx.x;

    const float4* src = (const float4*)(fm  + ((size_t)b * C_ + ch) * HW_);
    float4*       dst = (float4*)      (out + ((size_t)b * C_ + ch) * HW_);

    __shared__ float row[P_];
    __shared__ float s_w[K_ * 8], s_str[K_ * 8];
    __shared__ int   s_nbr[K_ * 8];
    __shared__ int   s_cpos[K_];

    float4 v = src[t];
    ((float4*)row)[t] = v;
    if (t < K_ * 8) {
        s_w[t]   = ((const float*)g_w[b])[t];
        s_str[t] = ((const float*)g_str[b])[t];
        s_nbr[t] = ((const int*)g_nbr[b])[t];
        if (t < K_) s_cpos[t] = g_cpos[b][t];
    }
    __syncthreads();

    const unsigned short* mp = g_map[b] + t * 4;
    float ov[4] = {v.x, v.y, v.z, v.w};
    float res[4];
#pragma unroll
    for (int u = 0; u < 4; u++) {
        unsigned short mv = mp[u];
        float r = ov[u];
        if (mv) {
            if (mv & 0x8000u) {                     // center -> weighted avg
                int slot = mv & 0xFF;
                float acc = 0.f;
#pragma unroll
                for (int j = 0; j < 8; j++)
                    acc += s_w[slot * 8 + j] * row[s_nbr[slot * 8 + j]];
                r = acc;
            } else {                                // winner -> nbr - str*center
                int slot = (mv >> 3) & 15;
                int j    = mv & 7;
                r = r - s_str[slot * 8 + j] * row[s_cpos[slot]];
            }
        }
        res[u] = r;
    }
    dst[t] = make_float4(res[0], res[1], res[2], res[3]);
}

// ---------------------------------------------------------------------------
extern "C" void kernel_launch(void* const* d_in, const int* in_sizes, int n_in,
                              void* d_out, int out_size) {
    const float* fm   = (const float*)d_in[0];
    const float* attn = (const float*)d_in[1];
    float* out = (float*)d_out;

    ratio_kernel<<<dim3(B_, P_ / 64), 1024>>>(attn);
    topk_kernel<<<B_, 32>>>();
    stats_kernel<<<B_ * K_, 256>>>(fm);
    apply_kernel<<<B_ * C_, 256>>>(fm, out);
}